// round 1
// baseline (speedup 1.0000x reference)
#include <cuda_runtime.h>

#define FID 65536
#define BATCH 2048
#define ROW_V4 (FID / 4)   // 16384 float4 per row

__global__ __launch_bounds__(256) void row_dot_kernel(
    const float* __restrict__ gate,
    const float* __restrict__ bias,
    const float* __restrict__ gbias,
    float* __restrict__ logits)
{
    const int row = blockIdx.x;
    const float4* __restrict__ g = reinterpret_cast<const float4*>(gate + (size_t)row * FID);
    const float4* __restrict__ b = reinterpret_cast<const float4*>(bias);

    float acc = 0.0f;
    // 256 threads, 16384 float4 -> 64 iterations per thread, coalesced, high MLP
    #pragma unroll 4
    for (int i = threadIdx.x; i < ROW_V4; i += 256) {
        float4 gv = g[i];
        float4 bv = b[i];
        acc = fmaf(gv.x, bv.x, acc);
        acc = fmaf(gv.y, bv.y, acc);
        acc = fmaf(gv.z, bv.z, acc);
        acc = fmaf(gv.w, bv.w, acc);
    }

    // warp reduce
    #pragma unroll
    for (int off = 16; off > 0; off >>= 1)
        acc += __shfl_down_sync(0xFFFFFFFFu, acc, off);

    __shared__ float smem[8];
    const int lane = threadIdx.x & 31;
    const int wid  = threadIdx.x >> 5;
    if (lane == 0) smem[wid] = acc;
    __syncthreads();

    if (wid == 0) {
        float v = (lane < 8) ? smem[lane] : 0.0f;
        #pragma unroll
        for (int off = 4; off > 0; off >>= 1)
            v += __shfl_down_sync(0xFFFFFFFFu, v, off);
        if (lane == 0) logits[row] = v + gbias[0];
    }
}

// One block: compute pred + summed BCE loss deterministically.
__global__ __launch_bounds__(1024) void epilogue_kernel(
    const float* __restrict__ logits,
    const float* __restrict__ label,
    float* __restrict__ pred,
    float* __restrict__ loss)
{
    __shared__ float smem[32];
    float lsum = 0.0f;

    for (int i = threadIdx.x; i < BATCH; i += 1024) {
        float z = logits[i];
        float y = label[i];
        pred[i] = 1.0f / (1.0f + __expf(-z));
        // max(z,0) - z*y + log1p(exp(-|z|))
        float per = fmaxf(z, 0.0f) - z * y + log1pf(expf(-fabsf(z)));
        lsum += per;
    }

    #pragma unroll
    for (int off = 16; off > 0; off >>= 1)
        lsum += __shfl_down_sync(0xFFFFFFFFu, lsum, off);

    const int lane = threadIdx.x & 31;
    const int wid  = threadIdx.x >> 5;
    if (lane == 0) smem[wid] = lsum;
    __syncthreads();

    if (wid == 0) {
        float v = (lane < 32) ? smem[lane] : 0.0f;
        #pragma unroll
        for (int off = 16; off > 0; off >>= 1)
            v += __shfl_down_sync(0xFFFFFFFFu, v, off);
        if (lane == 0) loss[0] = v;
    }
}

extern "C" void kernel_launch(void* const* d_in, const int* in_sizes, int n_in,
                              void* d_out, int out_size)
{
    // Inputs per setup_inputs order:
    // 0: bias_fid_gate [2048, 65536] f32
    // 1: sparse_bias   [65536] f32
    // 2: global_bias   [1] f32
    // 3: label         [2048] f32
    const float* gate  = (const float*)d_in[0];
    const float* bias  = (const float*)d_in[1];
    const float* gbias = (const float*)d_in[2];
    const float* label = (const float*)d_in[3];

    // Output: logits[2048], pred[2048], loss[1] concatenated
    float* out    = (float*)d_out;
    float* logits = out;
    float* pred   = out + BATCH;
    float* loss   = out + 2 * BATCH;

    row_dot_kernel<<<BATCH, 256>>>(gate, bias, gbias, logits);
    epilogue_kernel<<<1, 1024>>>(logits, label, pred, loss);
}